// round 13
// baseline (speedup 1.0000x reference)
#include <cuda_runtime.h>
#include <cuda_bf16.h>
#include <math.h>
#include <stdint.h>

// ---------------- problem constants ----------------
#define BB 256
#define SS 128
#define HH 768
#define NHH 8

// ---------------- scratch (static device globals; no runtime alloc) ----------------
__device__ float g_seqr[BB * HH];
__device__ float g_bufA[BB * 1536];
__device__ float g_bufB[BB * 1536];
__device__ float g_d1o[BB * 384];
__device__ float g_part[4718592];      // split-K partials

// pre-split hi/lo buffers (uint4 for 16B alignment)
__device__ uint4 g_hs_h[3145728],  g_hs_l[3145728];    // 32768*384 w
__device__ uint4 g_wqkv_h[221184], g_wqkv_l[221184];   // 2304*384 w
__device__ uint4 g_wout_h[73728],  g_wout_l[73728];    // 768*384 w
__device__ uint4 g_wf1_h[147456],  g_wf1_l[147456];    // 1536*384 w
__device__ uint4 g_wf2_h[294912],  g_wf2_l[294912];    // 1536*768 w
__device__ uint4 g_wc_h[147456],   g_wc_l[147456];     // 768*768 w
__device__ uint4 g_wr1_h[36864],   g_wr1_l[36864];     // 384*384 w
__device__ uint4 g_wd1_h[36864],   g_wd1_l[36864];     // 384*384 w
__device__ uint4 g_abar_h[24576],  g_abar_l[24576];    // 256*384 w
__device__ uint4 g_seqr_h[24576],  g_seqr_l[24576];    // 256*384 w
__device__ uint4 g_act1_h[49152],  g_act1_l[49152];
__device__ uint4 g_act2_h[49152],  g_act2_l[49152];
__device__ uint4 g_qkvs_h[9437184], g_qkvs_l[9437184]; // 32768*1152 w (split qkv)

// ---------------- bf16x2 split: pair (x0,x1) -> hi word + lo word ----------------
__device__ __forceinline__ void split2(float x0, float x1, uint32_t& h, uint32_t& l) {
    asm("cvt.rn.bf16x2.f32 %0, %1, %2;" : "=r"(h) : "f"(x1), "f"(x0));
    __nv_bfloat162 hb = *reinterpret_cast<__nv_bfloat162*>(&h);
    float h0 = __low2float(hb), h1 = __high2float(hb);
    asm("cvt.rn.bf16x2.f32 %0, %1, %2;" : "=r"(l) : "f"(x1 - h1), "f"(x0 - h0));
}

// ---------------- pre-split kernel ----------------
__global__ void presplit_k(const float* __restrict__ in, int ldaf, int Kf,
                           uint32_t* __restrict__ oh, uint32_t* __restrict__ ol, long total4)
{
    long idx = (long)blockIdx.x * blockDim.x + threadIdx.x;
    if (idx < total4) {
        int K4 = Kf >> 2;
        long row = idx / K4;
        int c4 = (int)(idx - row * K4);
        float4 v = *(const float4*)(in + row * ldaf + c4 * 4);
        uint32_t h0, l0, h1, l1;
        split2(v.x, v.y, h0, l0);
        split2(v.z, v.w, h1, l1);
        long w = row * (Kf >> 1) + c4 * 2;
        oh[w] = h0; oh[w + 1] = h1;
        ol[w] = l0; ol[w + 1] = l1;
    }
}

// ---------------- common GEMM macros ----------------
#define CPA(dst, src) \
    asm volatile("cp.async.cg.shared.global [%0], [%1], 16;" :: "r"(dst), "l"(src) : "memory")
#define CP_COMMIT() asm volatile("cp.async.commit_group;" ::: "memory")
#define CP_WAIT0()  asm volatile("cp.async.wait_group 0;" ::: "memory")
#define LDSM4(r0, r1, r2, r3, addr) \
    asm volatile("ldmatrix.sync.aligned.m8n8.x4.shared.b16 {%0,%1,%2,%3}, [%4];" \
                 : "=r"(r0), "=r"(r1), "=r"(r2), "=r"(r3) : "r"(addr))
#define MMA_BF16(acc, a0, a1, a2, a3, b0, b1) \
    asm("mma.sync.aligned.m16n8k16.row.col.f32.bf16.bf16.f32 " \
        "{%0,%1,%2,%3},{%4,%5,%6,%7},{%8,%9},{%0,%1,%2,%3};" \
        : "+f"((acc)[0]), "+f"((acc)[1]), "+f"((acc)[2]), "+f"((acc)[3]) \
        : "r"(a0), "r"(a1), "r"(a2), "r"(a3), "r"(b0), "r"(b1))

// pass-major mma schedule (nt=4): per-acc order ah*bl -> al*bh -> ah*bh.
#define MMA_TILE_MT(accrow, ah0, ah1, ah2, ah3, al0, al1, al2, al3, bh, bl) do { \
    MMA_BF16((accrow)[0], ah0, ah1, ah2, ah3, (bl)[0][0], (bl)[0][1]); \
    MMA_BF16((accrow)[1], ah0, ah1, ah2, ah3, (bl)[1][0], (bl)[1][1]); \
    MMA_BF16((accrow)[2], ah0, ah1, ah2, ah3, (bl)[2][0], (bl)[2][1]); \
    MMA_BF16((accrow)[3], ah0, ah1, ah2, ah3, (bl)[3][0], (bl)[3][1]); \
    MMA_BF16((accrow)[0], al0, al1, al2, al3, (bh)[0][0], (bh)[0][1]); \
    MMA_BF16((accrow)[1], al0, al1, al2, al3, (bh)[1][0], (bh)[1][1]); \
    MMA_BF16((accrow)[2], al0, al1, al2, al3, (bh)[2][0], (bh)[2][1]); \
    MMA_BF16((accrow)[3], al0, al1, al2, al3, (bh)[3][0], (bh)[3][1]); \
    MMA_BF16((accrow)[0], ah0, ah1, ah2, ah3, (bh)[0][0], (bh)[0][1]); \
    MMA_BF16((accrow)[1], ah0, ah1, ah2, ah3, (bh)[1][0], (bh)[1][1]); \
    MMA_BF16((accrow)[2], ah0, ah1, ah2, ah3, (bh)[2][0], (bh)[2][1]); \
    MMA_BF16((accrow)[3], ah0, ah1, ah2, ah3, (bh)[3][0], (bh)[3][1]); \
} while (0)

// pass-major for nt=0..7 (wide kernel)
#define MMA_TILE_MT8(accrow, ah0, ah1, ah2, ah3, al0, al1, al2, al3, bh, bl) do { \
    MMA_BF16((accrow)[0], ah0, ah1, ah2, ah3, (bl)[0][0], (bl)[0][1]); \
    MMA_BF16((accrow)[1], ah0, ah1, ah2, ah3, (bl)[1][0], (bl)[1][1]); \
    MMA_BF16((accrow)[2], ah0, ah1, ah2, ah3, (bl)[2][0], (bl)[2][1]); \
    MMA_BF16((accrow)[3], ah0, ah1, ah2, ah3, (bl)[3][0], (bl)[3][1]); \
    MMA_BF16((accrow)[4], ah0, ah1, ah2, ah3, (bl)[4][0], (bl)[4][1]); \
    MMA_BF16((accrow)[5], ah0, ah1, ah2, ah3, (bl)[5][0], (bl)[5][1]); \
    MMA_BF16((accrow)[6], ah0, ah1, ah2, ah3, (bl)[6][0], (bl)[6][1]); \
    MMA_BF16((accrow)[7], ah0, ah1, ah2, ah3, (bl)[7][0], (bl)[7][1]); \
    MMA_BF16((accrow)[0], al0, al1, al2, al3, (bh)[0][0], (bh)[0][1]); \
    MMA_BF16((accrow)[1], al0, al1, al2, al3, (bh)[1][0], (bh)[1][1]); \
    MMA_BF16((accrow)[2], al0, al1, al2, al3, (bh)[2][0], (bh)[2][1]); \
    MMA_BF16((accrow)[3], al0, al1, al2, al3, (bh)[3][0], (bh)[3][1]); \
    MMA_BF16((accrow)[4], al0, al1, al2, al3, (bh)[4][0], (bh)[4][1]); \
    MMA_BF16((accrow)[5], al0, al1, al2, al3, (bh)[5][0], (bh)[5][1]); \
    MMA_BF16((accrow)[6], al0, al1, al2, al3, (bh)[6][0], (bh)[6][1]); \
    MMA_BF16((accrow)[7], al0, al1, al2, al3, (bh)[7][0], (bh)[7][1]); \
    MMA_BF16((accrow)[0], ah0, ah1, ah2, ah3, (bh)[0][0], (bh)[0][1]); \
    MMA_BF16((accrow)[1], ah0, ah1, ah2, ah3, (bh)[1][0], (bh)[1][1]); \
    MMA_BF16((accrow)[2], ah0, ah1, ah2, ah3, (bh)[2][0], (bh)[2][1]); \
    MMA_BF16((accrow)[3], ah0, ah1, ah2, ah3, (bh)[3][0], (bh)[3][1]); \
    MMA_BF16((accrow)[4], ah0, ah1, ah2, ah3, (bh)[4][0], (bh)[4][1]); \
    MMA_BF16((accrow)[5], ah0, ah1, ah2, ah3, (bh)[5][0], (bh)[5][1]); \
    MMA_BF16((accrow)[6], ah0, ah1, ah2, ah3, (bh)[6][0], (bh)[6][1]); \
    MMA_BF16((accrow)[7], ah0, ah1, ah2, ah3, (bh)[7][0], (bh)[7][1]); \
} while (0)

// ---------------- WIDE bf16x2 GEMM for qkv: block 128x256, warp 64x64 ----------------
// 2-stage cp.async, 1 sync per K32 tile. smem per stage (words):
// AH[128x20]=2560 @0, AL @2560, BH[256x20]=5120 @5120, BL @10240. Stage=15360 w.
#define WSMW 20
#define WSTG 15360
#define WGEMM_SMEM (2 * WSTG * 4)   // 122880 B

__global__ void __launch_bounds__(256, 1) gemm_wide_k(
    const uint32_t* __restrict__ Ah, const uint32_t* __restrict__ Al, int ldaw,
    const uint32_t* __restrict__ Wh, const uint32_t* __restrict__ Wl, int ldww,
    const float* __restrict__ bias,
    uint32_t* __restrict__ Oh, uint32_t* __restrict__ Ol, int ldcw, int K)
{
    extern __shared__ uint32_t sm[];
    uint32_t smb;
    asm("{ .reg .u64 t; cvta.to.shared.u64 t, %1; cvt.u32.u64 %0, t; }" : "=r"(smb) : "l"(sm));

    int tid = threadIdx.x, warp = tid >> 5, lane = tid & 31;
    int wm = warp >> 2, wn = warp & 3, g = lane >> 2, t4 = lane & 3;

    // producer coords
    int lr = tid >> 1, hf = tid & 1;
    const uint32_t* pAH = Ah + (long)(blockIdx.y * 128 + lr) * ldaw + hf * 8;
    const uint32_t* pAL = Al + (long)(blockIdx.y * 128 + lr) * ldaw + hf * 8;
    const uint32_t* pWH = Wh + (long)(blockIdx.x * 256 + tid) * ldww;
    const uint32_t* pWL = Wl + (long)(blockIdx.x * 256 + tid) * ldww;
    uint32_t dstA = smb + (lr * WSMW + hf * 8) * 4;
    uint32_t dstB = smb + (5120 + tid * WSMW) * 4;

    int laneA = ((lane & 7) + ((lane >> 3) & 1) * 8 + wm * 64) * WSMW + ((lane >> 4) & 1) * 4;
    int laneB = ((lane & 7) + ((lane >> 4) & 1) * 8 + wn * 64) * WSMW + ((lane >> 3) & 1) * 4;

    float acc[4][8][4];
#pragma unroll
    for (int i = 0; i < 4; i++)
#pragma unroll
        for (int j = 0; j < 8; j++)
#pragma unroll
            for (int e = 0; e < 4; e++) acc[i][j][e] = 0.0f;

    auto prod = [&](int t, int s) {
        uint32_t da = dstA + s * (WSTG * 4);
        const uint32_t* p = pAH + t * 16;
        CPA(da, p); CPA(da + 16, p + 4);
        p = pAL + t * 16;
        CPA(da + 2560 * 4, p); CPA(da + 2560 * 4 + 16, p + 4);
        uint32_t db = dstB + s * (WSTG * 4);
        p = pWH + t * 16;
        CPA(db, p); CPA(db + 16, p + 4); CPA(db + 32, p + 8); CPA(db + 48, p + 12);
        p = pWL + t * 16;
        CPA(db + 5120 * 4, p); CPA(db + 5120 * 4 + 16, p + 4);
        CPA(db + 5120 * 4 + 32, p + 8); CPA(db + 5120 * 4 + 48, p + 12);
    };

    int T = K >> 5;
    prod(0, 0); CP_COMMIT();

    for (int t = 0; t < T; t++) {
        CP_WAIT0();
        __syncthreads();
        if (t + 1 < T) prod(t + 1, (t + 1) & 1);
        CP_COMMIT();

        uint32_t sb = smb + (t & 1) * (WSTG * 4);
        uint32_t aH_ = sb + laneA * 4;
        uint32_t aL_ = aH_ + 2560 * 4;
        uint32_t bH_ = sb + 5120 * 4 + laneB * 4;
        uint32_t bL_ = bH_ + 5120 * 4;
#pragma unroll
        for (int ks = 0; ks < 2; ks++) {
            uint32_t ko = ks * 32;   // 8 words
            uint32_t bh[8][2], bl[8][2];
            LDSM4(bh[0][0], bh[0][1], bh[1][0], bh[1][1], bH_ + ko);
            LDSM4(bh[2][0], bh[2][1], bh[3][0], bh[3][1], bH_ + ko + 16 * WSMW * 4);
            LDSM4(bh[4][0], bh[4][1], bh[5][0], bh[5][1], bH_ + ko + 32 * WSMW * 4);
            LDSM4(bh[6][0], bh[6][1], bh[7][0], bh[7][1], bH_ + ko + 48 * WSMW * 4);
            LDSM4(bl[0][0], bl[0][1], bl[1][0], bl[1][1], bL_ + ko);
            LDSM4(bl[2][0], bl[2][1], bl[3][0], bl[3][1], bL_ + ko + 16 * WSMW * 4);
            LDSM4(bl[4][0], bl[4][1], bl[5][0], bl[5][1], bL_ + ko + 32 * WSMW * 4);
            LDSM4(bl[6][0], bl[6][1], bl[7][0], bl[7][1], bL_ + ko + 48 * WSMW * 4);
#pragma unroll
            for (int mt = 0; mt < 4; mt++) {
                uint32_t ah0, ah1, ah2, ah3, al0, al1, al2, al3;
                LDSM4(ah0, ah1, ah2, ah3, aH_ + ko + mt * (16 * WSMW * 4));
                LDSM4(al0, al1, al2, al3, aL_ + ko + mt * (16 * WSMW * 4));
                MMA_TILE_MT8(acc[mt], ah0, ah1, ah2, ah3, al0, al1, al2, al3, bh, bl);
            }
        }
    }

    __syncthreads();
    // epilogue: split-bf16x2 output
#pragma unroll
    for (int mt = 0; mt < 4; mt++) {
        int r0 = wm * 64 + mt * 16 + g;
#pragma unroll
        for (int nt = 0; nt < 8; nt++) {
            int c = wn * 64 + nt * 8 + 2 * t4;
            float b0 = bias[blockIdx.x * 256 + c];
            float b1 = bias[blockIdx.x * 256 + c + 1];
            long cw = (long)(blockIdx.x * 256 + c) >> 1;
            uint32_t hw, lw;
            split2(acc[mt][nt][0] + b0, acc[mt][nt][1] + b1, hw, lw);
            long w0 = (long)(blockIdx.y * 128 + r0) * ldcw + cw;
            Oh[w0] = hw; Ol[w0] = lw;
            split2(acc[mt][nt][2] + b0, acc[mt][nt][3] + b1, hw, lw);
            long w1 = (long)(blockIdx.y * 128 + r0 + 8) * ldcw + cw;
            Oh[w1] = hw; Ol[w1] = lw;
        }
    }
}

// ---------------- 128x128 bf16x2 GEMM (proven engine; chain + internal use) ----------------
#define SMW 20
#define ARR 2560
#define STG 10240
#define GEMM_SMEM (2 * STG * 4)    // 81920 B

__global__ void __launch_bounds__(256, 2) gemm_sp_k(
    const uint32_t* __restrict__ Ah, const uint32_t* __restrict__ Al, int ldaw,
    const uint32_t* __restrict__ Wh, const uint32_t* __restrict__ Wl, int ldww,
    int kchunkw,
    const float* __restrict__ bias, float* __restrict__ C,
    uint32_t* __restrict__ Oh, uint32_t* __restrict__ Ol,
    int ldc, long sC, int K, int zdiv)
{
    extern __shared__ uint32_t sm[];
    uint32_t smb;
    asm("{ .reg .u64 t; cvta.to.shared.u64 t, %1; cvt.u32.u64 %0, t; }" : "=r"(smb) : "l"(sm));

    int z = blockIdx.z;
    int koffw = (z % zdiv) * kchunkw;

    int tid = threadIdx.x, warp = tid >> 5, lane = tid & 31;
    int wm = warp >> 2, wn = warp & 3, g = lane >> 2, t4 = lane & 3;

    int lr = tid >> 1, hf = tid & 1;
    const uint32_t* pAH = Ah + (long)(blockIdx.y * 128 + lr) * ldaw + koffw + hf * 8;
    const uint32_t* pAL = Al + (long)(blockIdx.y * 128 + lr) * ldaw + koffw + hf * 8;
    const uint32_t* pWH = Wh + (long)(blockIdx.x * 128 + lr) * ldww + koffw + hf * 8;
    const uint32_t* pWL = Wl + (long)(blockIdx.x * 128 + lr) * ldww + koffw + hf * 8;
    uint32_t dstB = smb + (lr * SMW + hf * 8) * 4;

    int laneA = ((lane & 7) + ((lane >> 3) & 1) * 8 + wm * 64) * SMW + ((lane >> 4) & 1) * 4;
    int laneB = ((lane & 7) + ((lane >> 4) & 1) * 8 + wn * 32) * SMW + ((lane >> 3) & 1) * 4;

    float acc[4][4][4];
#pragma unroll
    for (int i = 0; i < 4; i++)
#pragma unroll
        for (int j = 0; j < 4; j++)
#pragma unroll
            for (int e = 0; e < 4; e++) acc[i][j][e] = 0.0f;

    auto prod = [&](int t, int s) {
        uint32_t d = dstB + s * (STG * 4);
        const uint32_t* p = pAH + t * 16;
        CPA(d, p); CPA(d + 16, p + 4);
        p = pAL + t * 16;
        CPA(d + ARR * 4, p); CPA(d + ARR * 4 + 16, p + 4);
        p = pWH + t * 16;
        CPA(d + 2 * ARR * 4, p); CPA(d + 2 * ARR * 4 + 16, p + 4);
        p = pWL + t * 16;
        CPA(d + 3 * ARR * 4, p); CPA(d + 3 * ARR * 4 + 16, p + 4);
    };

    int T = K >> 5;
    prod(0, 0); CP_COMMIT();

    for (int t = 0; t < T; t++) {
        CP_WAIT0();
        __syncthreads();
        if (t + 1 < T) prod(t + 1, (t + 1) & 1);
        CP_COMMIT();

        uint32_t sb = smb + (t & 1) * (STG * 4);
        uint32_t aH_ = sb + laneA * 4;
        uint32_t aL_ = aH_ + ARR * 4;
        uint32_t bH_ = sb + 2 * ARR * 4 + laneB * 4;
        uint32_t bL_ = bH_ + ARR * 4;
#pragma unroll
        for (int ks = 0; ks < 2; ks++) {
            uint32_t ko = ks * 32;
            uint32_t bh[4][2], bl[4][2];
            LDSM4(bh[0][0], bh[0][1], bh[1][0], bh[1][1], bH_ + ko);
            LDSM4(bh[2][0], bh[2][1], bh[3][0], bh[3][1], bH_ + ko + 16 * SMW * 4);
            LDSM4(bl[0][0], bl[0][1], bl[1][0], bl[1][1], bL_ + ko);
            LDSM4(bl[2][0], bl[2][1], bl[3][0], bl[3][1], bL_ + ko + 16 * SMW * 4);
#pragma unroll
            for (int mt = 0; mt < 4; mt++) {
                uint32_t ah0, ah1, ah2, ah3, al0, al1, al2, al3;
                LDSM4(ah0, ah1, ah2, ah3, aH_ + ko + mt * (16 * SMW * 4));
                LDSM4(al0, al1, al2, al3, aL_ + ko + mt * (16 * SMW * 4));
                MMA_TILE_MT(acc[mt], ah0, ah1, ah2, ah3, al0, al1, al2, al3, bh, bl);
            }
        }
    }

    __syncthreads();
    if (Oh) {
        int ldcw = ldc >> 1;
#pragma unroll
        for (int mt = 0; mt < 4; mt++) {
            int r0 = wm * 64 + mt * 16 + g;
#pragma unroll
            for (int nt = 0; nt < 4; nt++) {
                int c = wn * 32 + nt * 8 + 2 * t4;
                float b0 = bias ? bias[blockIdx.x * 128 + c] : 0.f;
                float b1 = bias ? bias[blockIdx.x * 128 + c + 1] : 0.f;
                long cw = (long)(blockIdx.x * 128 + c) >> 1;
                uint32_t hw, lw;
                split2(acc[mt][nt][0] + b0, acc[mt][nt][1] + b1, hw, lw);
                long w0 = (long)(blockIdx.y * 128 + r0) * ldcw + cw;
                Oh[w0] = hw; Ol[w0] = lw;
                split2(acc[mt][nt][2] + b0, acc[mt][nt][3] + b1, hw, lw);
                long w1 = (long)(blockIdx.y * 128 + r0 + 8) * ldcw + cw;
                Oh[w1] = hw; Ol[w1] = lw;
            }
        }
    } else {
        float* Cb = C + (long)z * sC + (long)blockIdx.y * 128 * ldc + blockIdx.x * 128;
#pragma unroll
        for (int mt = 0; mt < 4; mt++) {
            int r0 = wm * 64 + mt * 16 + g;
#pragma unroll
            for (int nt = 0; nt < 4; nt++) {
                int c = wn * 32 + nt * 8 + 2 * t4;
                float b0 = 0.f, b1 = 0.f;
                if (bias) { b0 = bias[blockIdx.x * 128 + c]; b1 = bias[blockIdx.x * 128 + c + 1]; }
                float* p0 = Cb + (long)r0 * ldc + c;
                float* p1 = Cb + (long)(r0 + 8) * ldc + c;
                p0[0] = acc[mt][nt][0] + b0; p0[1] = acc[mt][nt][1] + b1;
                p1[0] = acc[mt][nt][2] + b0; p1[1] = acc[mt][nt][3] + b1;
            }
        }
    }
}

// ---------------- fused attention per head, consuming pre-split qkv ----------------
#define ATTN_SMEM GEMM_SMEM
__global__ void __launch_bounds__(256, 2) attn_fused_k(
    const uint32_t* __restrict__ qh, const uint32_t* __restrict__ ql,
    uint32_t* __restrict__ abh, uint32_t* __restrict__ abl)
{
    extern __shared__ uint32_t sm[];
    uint32_t smb;
    asm("{ .reg .u64 t; cvta.to.shared.u64 t, %1; cvt.u32.u64 %0, t; }" : "=r"(smb) : "l"(sm));

    int bhid = blockIdx.x;
    int b = bhid >> 3, h = bhid & 7;

    int tid = threadIdx.x, warp = tid >> 5, lane = tid & 31;
    int wm = warp >> 2, wn = warp & 3, g = lane >> 2, t4 = lane & 3;

    int lr = tid >> 1, hf = tid & 1;
    long rowbase = ((long)b * 128 + lr) * 1152 + h * 48 + hf * 8;
    const uint32_t* pQH = qh + rowbase;
    const uint32_t* pQL = ql + rowbase;
    const uint32_t* pKH = qh + rowbase + 384;
    const uint32_t* pKL = ql + rowbase + 384;
    uint32_t dstB = smb + (lr * SMW + hf * 8) * 4;

    int laneA = ((lane & 7) + ((lane >> 3) & 1) * 8 + wm * 64) * SMW + ((lane >> 4) & 1) * 4;
    int laneB = ((lane & 7) + ((lane >> 4) & 1) * 8 + wn * 32) * SMW + ((lane >> 3) & 1) * 4;

    float acc[4][4][4];
#pragma unroll
    for (int i = 0; i < 4; i++)
#pragma unroll
        for (int j = 0; j < 4; j++)
#pragma unroll
            for (int e = 0; e < 4; e++) acc[i][j][e] = 0.0f;

    auto prod = [&](int t, int s) {
        uint32_t d = dstB + s * (STG * 4);
        const uint32_t* p = pQH + t * 16;
        CPA(d, p); CPA(d + 16, p + 4);
        p = pQL + t * 16;
        CPA(d + ARR * 4, p); CPA(d + ARR * 4 + 16, p + 4);
        p = pKH + t * 16;
        CPA(d + 2 * ARR * 4, p); CPA(d + 2 * ARR * 4 + 16, p + 4);
        p = pKL + t * 16;
        CPA(d + 3 * ARR * 4, p); CPA(d + 3 * ARR * 4 + 16, p + 4);
    };

    const int T = 3;
    prod(0, 0); CP_COMMIT();

    for (int t = 0; t < T; t++) {
        CP_WAIT0();
        __syncthreads();
        if (t + 1 < T) prod(t + 1, (t + 1) & 1);
        CP_COMMIT();

        uint32_t sb = smb + (t & 1) * (STG * 4);
        uint32_t aH_ = sb + laneA * 4;
        uint32_t aL_ = aH_ + ARR * 4;
        uint32_t bH_ = sb + 2 * ARR * 4 + laneB * 4;
        uint32_t bL_ = bH_ + ARR * 4;
#pragma unroll
        for (int ks = 0; ks < 2; ks++) {
            uint32_t ko = ks * 32;
            uint32_t bh[4][2], bl[4][2];
            LDSM4(bh[0][0], bh[0][1], bh[1][0], bh[1][1], bH_ + ko);
            LDSM4(bh[2][0], bh[2][1], bh[3][0], bh[3][1], bH_ + ko + 16 * SMW * 4);
            LDSM4(bl[0][0], bl[0][1], bl[1][0], bl[1][1], bL_ + ko);
            LDSM4(bl[2][0], bl[2][1], bl[3][0], bl[3][1], bL_ + ko + 16 * SMW * 4);
#pragma unroll
            for (int mt = 0; mt < 4; mt++) {
                uint32_t ah0, ah1, ah2, ah3, al0, al1, al2, al3;
                LDSM4(ah0, ah1, ah2, ah3, aH_ + ko + mt * (16 * SMW * 4));
                LDSM4(al0, al1, al2, al3, aL_ + ko + mt * (16 * SMW * 4));
                MMA_TILE_MT(acc[mt], ah0, ah1, ah2, ah3, al0, al1, al2, al3, bh, bl);
            }
        }
    }
    __syncthreads();

    const float scale = 0.10206207261596577f;   // 1/sqrt(96)
    float* sc = (float*)sm;
    float* wa = (float*)(sm + 128 * 132);
    float* wp = wa + 8 * 128;
#pragma unroll
    for (int mt = 0; mt < 4; mt++) {
        int r0 = wm * 64 + mt * 16 + g;
#pragma unroll
        for (int nt = 0; nt < 4; nt++) {
            int c = wn * 32 + nt * 8 + 2 * t4;
            sc[r0 * 132 + c]           = acc[mt][nt][0] * scale;
            sc[r0 * 132 + c + 1]       = acc[mt][nt][1] * scale;
            sc[(r0 + 8) * 132 + c]     = acc[mt][nt][2] * scale;
            sc[(r0 + 8) * 132 + c + 1] = acc[mt][nt][3] * scale;
        }
    }
    __syncthreads();

#pragma unroll
    for (int j = 0; j < 4; j++) wa[warp * 128 + lane + 32 * j] = 0.0f;
    __syncwarp();

    for (int s = warp; s < 128; s += 8) {
        float x0 = sc[s * 132 + lane];
        float x1 = sc[s * 132 + lane + 32];
        float x2 = sc[s * 132 + lane + 64];
        float x3 = sc[s * 132 + lane + 96];
        float m = fmaxf(fmaxf(x0, x1), fmaxf(x2, x3));
#pragma unroll
        for (int o = 16; o; o >>= 1) m = fmaxf(m, __shfl_xor_sync(0xffffffffu, m, o));
        float e0 = expf(x0 - m), e1 = expf(x1 - m), e2 = expf(x2 - m), e3 = expf(x3 - m);
        float smm = e0 + e1 + e2 + e3;
#pragma unroll
        for (int o = 16; o; o >>= 1) smm += __shfl_xor_sync(0xffffffffu, smm, o);
        float inv = 1.0f / smm;
        wa[warp * 128 + lane]      += e0 * inv;
        wa[warp * 128 + lane + 32] += e1 * inv;
        wa[warp * 128 + lane + 64] += e2 * inv;
        wa[warp * 128 + lane + 96] += e3 * inv;
    }
    __syncthreads();
    if (warp == 0) {
#pragma unroll
        for (int j = 0; j < 4; j++) {
            int c = lane + 32 * j;
            float s = 0.f;
#pragma unroll
            for (int w = 0; w < 8; w++) s += wa[w * 128 + c];
            wa[c] = s;
        }
    }
    __syncthreads();

    if (tid < 192) {
        int p = tid % 48;
        int ks = tid / 48;
        long vbase = (long)b * 128 * 1152 + 768 + h * 48 + p;
        float a0 = 0.f, a1 = 0.f;
#pragma unroll 4
        for (int k = ks * 32; k < ks * 32 + 32; k++) {
            uint32_t vh = qh[vbase + (long)k * 1152];
            uint32_t vl = ql[vbase + (long)k * 1152];
            __nv_bfloat162 vhb = *reinterpret_cast<__nv_bfloat162*>(&vh);
            __nv_bfloat162 vlb = *reinterpret_cast<__nv_bfloat162*>(&vl);
            float w = wa[k];
            a0 = fmaf(w, __low2float(vhb), a0);
            a0 = fmaf(w, __low2float(vlb), a0);
            a1 = fmaf(w, __high2float(vhb), a1);
            a1 = fmaf(w, __high2float(vlb), a1);
        }
        wp[ks * 96 + 2 * p]     = a0;
        wp[ks * 96 + 2 * p + 1] = a1;
    }
    __syncthreads();
    if (tid < 48) {
        float a0 = ((wp[2 * tid] + wp[96 + 2 * tid]) + wp[192 + 2 * tid]) + wp[288 + 2 * tid];
        float a1 = ((wp[2 * tid + 1] + wp[96 + 2 * tid + 1]) + wp[192 + 2 * tid + 1]) + wp[288 + 2 * tid + 1];
        a0 *= (1.0f / 128.0f);
        a1 *= (1.0f / 128.0f);
        uint32_t hw, lw;
        split2(a0, a1, hw, lw);
        long w = (long)b * 384 + h * 48 + tid;
        abh[w] = hw;
        abl[w] = lw;
    }
}

// ---------------- split-K reduction (pairwise; optional split output) ----------------
__global__ void reduce_k(const float* __restrict__ part, int Z, long stride,
                         const float* __restrict__ bias, int N,
                         float* __restrict__ C, uint32_t* __restrict__ Ch,
                         uint32_t* __restrict__ Cl, int totalPairs)
{
    int p = blockIdx.x * blockDim.x + threadIdx.x;
    if (p < totalPairs) {
        int i0 = 2 * p;
        float s0 = 0.f, s1 = 0.f;
        for (int zz = 0; zz < Z; zz++) {
            s0 += part[(long)zz * stride + i0];
            s1 += part[(long)zz * stride + i0 + 1];
        }
        s0 += bias[i0 % N];
        s1 += bias[(i0 + 1) % N];
        C[i0] = s0; C[i0 + 1] = s1;
        if (Ch) {
            uint32_t hw, lw;
            split2(s0, s1, hw, lw);
            Ch[p] = hw; Cl[p] = lw;
        }
    }
}

// ---------------- fused split-K reduce + LayerNorm + GELU (+ optional split) ----------------
__global__ void redln_k(const float* __restrict__ part, int Z, long stride,
                        const float* __restrict__ bias,
                        const float* __restrict__ gm, const float* __restrict__ be,
                        float* __restrict__ outF,
                        uint32_t* __restrict__ oh, uint32_t* __restrict__ ol, int N)
{
    __shared__ float buf[1536];
    __shared__ float rs[8], rs2[8], sm_mean, sm_rstd;
    int row = blockIdx.x;
    int tid = threadIdx.x, warp = tid >> 5, lane = tid & 31;
    const float* pb = part + (long)row * N;

    float s = 0.f, s2 = 0.f;
    for (int i = tid; i < N; i += blockDim.x) {
        float v = 0.f;
        for (int zz = 0; zz < Z; zz++) v += pb[(long)zz * stride + i];
        v += bias[i];
        buf[i] = v;
        s += v; s2 += v * v;
    }
#pragma unroll
    for (int o = 16; o; o >>= 1) { s += __shfl_xor_sync(0xffffffffu, s, o); s2 += __shfl_xor_sync(0xffffffffu, s2, o); }
    if (lane == 0) { rs[warp] = s; rs2[warp] = s2; }
    __syncthreads();
    if (tid == 0) {
        float S = 0.f, S2 = 0.f;
        for (int w = 0; w < 8; w++) { S += rs[w]; S2 += rs2[w]; }
        float mean = S / N;
        float var = S2 / N - mean * mean;
        sm_mean = mean;
        sm_rstd = rsqrtf(var + 1e-5f);
    }
    __syncthreads();
    float mean = sm_mean, rstd = sm_rstd;
    int half = N >> 1;
    for (int p = tid; p < half; p += blockDim.x) {
        float v0 = (buf[2 * p] - mean) * rstd * gm[2 * p] + be[2 * p];
        float v1 = (buf[2 * p + 1] - mean) * rstd * gm[2 * p + 1] + be[2 * p + 1];
        v0 = 0.5f * v0 * (1.0f + erff(v0 * 0.70710678118654752f));
        v1 = 0.5f * v1 * (1.0f + erff(v1 * 0.70710678118654752f));
        outF[(long)row * N + 2 * p] = v0;
        outF[(long)row * N + 2 * p + 1] = v1;
        if (oh) {
            uint32_t hw, lw;
            split2(v0, v1, hw, lw);
            oh[(long)row * half + p] = hw;
            ol[(long)row * half + p] = lw;
        }
    }
}

// ---------------- warp dot helper ----------------
__device__ __forceinline__ float warp_dot(const float* a, const float* b, int n, int lane)
{
    float s = 0.f;
    for (int i = lane; i < n; i += 32) s = fmaf(a[i], b[i], s);
#pragma unroll
    for (int o = 16; o; o >>= 1) s += __shfl_xor_sync(0xffffffffu, s, o);
    return s;
}

// ---------------- small 5-way head (domain logits) ----------------
__global__ void head5_kernel(const float* __restrict__ in, int Kin,
                             const float* __restrict__ w, const float* __restrict__ bias,
                             float* __restrict__ out)
{
    int b = blockIdx.x, warp = threadIdx.x >> 5, lane = threadIdx.x & 31;
    if (warp < 5) {
        float s = warp_dot(in + (long)b * Kin, w + (long)warp * Kin, Kin, lane);
        if (lane == 0) out[b * 5 + warp] = s + bias[warp];
    }
}

// ---------------- gating softmax + top-2 + expert mix ----------------
__global__ void gate_kernel(const float* __restrict__ r1o,
                            const float* __restrict__ w_r2, const float* __restrict__ b_r2,
                            const float* __restrict__ hs,
                            const float* __restrict__ w_e, const float* __restrict__ b_e,
                            float* __restrict__ out)
{
    __shared__ float gl[5], ae[10];
    int b = blockIdx.x, tid = threadIdx.x, warp = tid >> 5, lane = tid & 31;

    if (warp < 5) {
        float s = warp_dot(r1o + (long)b * 384, w_r2 + (long)warp * 384, 384, lane);
        if (lane == 0) gl[warp] = s + b_r2[warp];
    }
    const float* cls = hs + (long)b * SS * HH;
    for (int idx = warp; idx < 10; idx += 8) {
        float s = warp_dot(cls, w_e + (long)idx * HH, HH, lane);
        if (lane == 0) ae[idx] = s + b_e[idx];
    }
    __syncthreads();

    if (tid == 0) {
        float m = gl[0];
        for (int j = 1; j < 5; j++) m = fmaxf(m, gl[j]);
        float e[5], sum = 0.f;
        for (int j = 0; j < 5; j++) { e[j] = expf(gl[j] - m); sum += e[j]; }
        float p[5];
        for (int j = 0; j < 5; j++) { p[j] = e[j] / sum; out[512 + b * 5 + j] = p[j]; }
        int i1 = 0;
        for (int j = 1; j < 5; j++) if (p[j] > p[i1]) i1 = j;
        int i2 = -1;
        for (int j = 0; j < 5; j++) if (j != i1 && (i2 < 0 || p[j] > p[i2])) i2 = j;
        float ps = p[i1] + p[i2];
        float w1 = p[i1] / ps, w2 = p[i2] / ps;
        for (int ee = 0; ee < 5; ee++) {
            bool sel = (ee == i1) || (ee == i2);
            out[1792 + b * 10 + ee * 2 + 0] = sel ? ae[ee * 2 + 0] : 0.0f;
            out[1792 + b * 10 + ee * 2 + 1] = sel ? ae[ee * 2 + 1] : 0.0f;
        }
        out[b * 2 + 0] = w1 * ae[i1 * 2 + 0] + w2 * ae[i2 * 2 + 0];
        out[b * 2 + 1] = w1 * ae[i1 * 2 + 1] + w2 * ae[i2 * 2 + 1];
    }
}

// ---------------- host launcher ----------------
extern "C" void kernel_launch(void* const* d_in, const int* in_sizes, int n_in,
                              void* d_out, int out_size)
{
    const float* hs    = (const float*)d_in[0];
    const float* w_qkv = (const float*)d_in[1];
    const float* b_qkv = (const float*)d_in[2];
    const float* w_out = (const float*)d_in[3];
    const float* b_out = (const float*)d_in[4];
    const float* w_f1  = (const float*)d_in[5];
    const float* b_f1  = (const float*)d_in[6];
    const float* gf1   = (const float*)d_in[7];
    const float* bef1  = (const float*)d_in[8];
    const float* w_f2  = (const float*)d_in[9];
    const float* b_f2  = (const float*)d_in[10];
    const float* gf2   = (const float*)d_in[11];
    const float* bef2  = (const float*)d_in[12];
    const float* w_c   = (const float*)d_in[13];
    const float* b_c   = (const float*)d_in[14];
    const float* gc    = (const float*)d_in[15];
    const float* bec   = (const float*)d_in[16];
    const float* w_r1  = (const float*)d_in[17];
    const float* b_r1  = (const float*)d_in[18];
    const float* gr1   = (const float*)d_in[19];
    const float* ber1  = (const float*)d_in[20];
    const float* w_r2  = (const float*)d_in[21];
    const float* b_r2  = (const float*)d_in[22];
    const float* w_d1  = (const float*)d_in[23];
    const float* b_d1  = (const float*)d_in[24];
    const float* gd1   = (const float*)d_in[25];
    const float* bed1  = (const float*)d_in[26];
    const float* w_d2  = (const float*)d_in[27];
    const float* b_d2  = (const float*)d_in[28];
    const float* w_e   = (const float*)d_in[29];
    const float* b_e   = (const float*)d_in[30];
    float* out = (float*)d_out;

    float *seqr, *bufA, *bufB, *d1o, *part;
    cudaGetSymbolAddress((void**)&seqr,  g_seqr);
    cudaGetSymbolAddress((void**)&bufA,  g_bufA);
    cudaGetSymbolAddress((void**)&bufB,  g_bufB);
    cudaGetSymbolAddress((void**)&d1o,   g_d1o);
    cudaGetSymbolAddress((void**)&part,  g_part);

    uint32_t *hsh, *hsl, *qkh, *qkl, *outh, *outl, *f1h, *f1l, *f2h, *f2l;
    uint32_t *ch, *cl, *r1h, *r1l, *d1h, *d1l, *abh, *abl, *sqh, *sql;
    uint32_t *a1h, *a1l, *a2h, *a2l, *qvh, *qvl;
    cudaGetSymbolAddress((void**)&hsh, g_hs_h);   cudaGetSymbolAddress((void**)&hsl, g_hs_l);
    cudaGetSymbolAddress((void**)&qkh, g_wqkv_h); cudaGetSymbolAddress((void**)&qkl, g_wqkv_l);
    cudaGetSymbolAddress((void**)&outh, g_wout_h); cudaGetSymbolAddress((void**)&outl, g_wout_l);
    cudaGetSymbolAddress((void**)&f1h, g_wf1_h);  cudaGetSymbolAddress((void**)&f1l, g_wf1_l);
    cudaGetSymbolAddress((void**)&f2h, g_wf2_h);  cudaGetSymbolAddress((void**)&f2l, g_wf2_l);
    cudaGetSymbolAddress((void**)&ch,  g_wc_h);   cudaGetSymbolAddress((void**)&cl,  g_wc_l);
    cudaGetSymbolAddress((void**)&r1h, g_wr1_h);  cudaGetSymbolAddress((void**)&r1l, g_wr1_l);
    cudaGetSymbolAddress((void**)&d1h, g_wd1_h);  cudaGetSymbolAddress((void**)&d1l, g_wd1_l);
    cudaGetSymbolAddress((void**)&abh, g_abar_h); cudaGetSymbolAddress((void**)&abl, g_abar_l);
    cudaGetSymbolAddress((void**)&sqh, g_seqr_h); cudaGetSymbolAddress((void**)&sql, g_seqr_l);
    cudaGetSymbolAddress((void**)&a1h, g_act1_h); cudaGetSymbolAddress((void**)&a1l, g_act1_l);
    cudaGetSymbolAddress((void**)&a2h, g_act2_h); cudaGetSymbolAddress((void**)&a2l, g_act2_l);
    cudaGetSymbolAddress((void**)&qvh, g_qkvs_h); cudaGetSymbolAddress((void**)&qvl, g_qkvs_l);

    cudaFuncSetAttribute(gemm_sp_k,    cudaFuncAttributeMaxDynamicSharedMemorySize, GEMM_SMEM);
    cudaFuncSetAttribute(gemm_wide_k,  cudaFuncAttributeMaxDynamicSharedMemorySize, WGEMM_SMEM);
    cudaFuncSetAttribute(attn_fused_k, cudaFuncAttributeMaxDynamicSharedMemorySize, ATTN_SMEM);

    auto split = [&](const float* in, int lda, int M, int K, uint32_t* oh, uint32_t* ol) {
        long t4 = (long)M * K / 4;
        presplit_k<<<(unsigned)((t4 + 255) / 256), 256>>>(in, lda, K, oh, ol, t4);
    };

    // 0-2: pre-split hs / w_qkv / w_d1  (qkv at launch idx 3 for ncu capture)
    split(hs,    768, 32768, 768, hsh, hsl);
    split(w_qkv, 768, 2304,  768, qkh, qkl);
    split(w_d1,  768, 384,   768, d1h, d1l);

    // 3: qkv = hs @ w_qkv.T + b_qkv  -> split output, WIDE engine (128x256 tiles)
    gemm_wide_k<<<dim3(2304 / 256, 32768 / 128, 1), 256, WGEMM_SMEM>>>(
        hsh, hsl, 384, qkh, qkl, 384, b_qkv, qvh, qvl, 1152, 768);

    // remaining weight pre-splits
    split(w_out, 768,  768,  768,  outh, outl);
    split(w_f1,  768,  1536, 768,  f1h,  f1l);
    split(w_f2,  1536, 1536, 1536, f2h,  f2l);
    split(w_c,   1536, 768,  1536, ch,   cl);
    split(w_r1,  768,  384,  768,  r1h,  r1l);

    // split-K GEMM (Kc = 128 -> kchunkw = 64) -> float partials
    auto gemm_part = [&](const uint32_t* Ah, const uint32_t* Al, int ldaw,
                         const uint32_t* Wh, const uint32_t* Wl, int ldww,
                         int N, int K) {
        int Z = K / 128;
        dim3 grid(N / 128, BB / 128, Z);
        gemm_sp_k<<<grid, 256, GEMM_SMEM>>>(
            Ah, Al, ldaw, Wh, Wl, ldww, 64, nullptr, part, nullptr, nullptr,
            N, (long)BB * N, 128, Z);
        return Z;
    };

    auto gemm_ln = [&](const uint32_t* Ah, const uint32_t* Al, int ldaw,
                       const uint32_t* Wh, const uint32_t* Wl, int ldww,
                       const float* bias, const float* gm, const float* be,
                       float* outF, uint32_t* oh, uint32_t* ol, int N, int K) {
        int Z = gemm_part(Ah, Al, ldaw, Wh, Wl, ldww, N, K);
        redln_k<<<BB, 256>>>(part, Z, (long)BB * N, bias, gm, be, outF, oh, ol, N);
    };

    // domain path
    gemm_ln(hsh, hsl, SS * 384, d1h, d1l, 384, b_d1, gd1, bed1, d1o, nullptr, nullptr, 384, 768);
    head5_kernel<<<BB, 160>>>(d1o, 384, w_d2, b_d2, out + 4352);

    // fused attention (pre-split qkv) -> abar (split)
    attn_fused_k<<<BB * NHH, 256, ATTN_SMEM>>>(qvh, qvl, abh, abl);

    // seq_repr = abar @ w_out.T + b_out
    {
        int Z = gemm_part(abh, abl, 384, outh, outl, 384, 768, 768);
        int pairs = BB * 768 / 2;
        reduce_k<<<(pairs + 255) / 256, 256>>>(part, Z, (long)BB * 768, b_out, 768,
                                               seqr, sqh, sql, pairs);
    }

    // f1 -> f2 -> ctx -> r1 chain
    gemm_ln(sqh, sql, 384, f1h, f1l, 384, b_f1, gf1, bef1, bufA, a1h, a1l, 1536, 768);
    gemm_ln(a1h, a1l, 768, f2h, f2l, 768, b_f2, gf2, bef2, bufA, a2h, a2l, 1536, 1536);
    gemm_ln(a2h, a2l, 768, ch, cl, 768, b_c, gc, bec, bufA, a1h, a1l, 768, 1536);
    gemm_ln(a1h, a1l, 384, r1h, r1l, 384, b_r1, gr1, ber1, bufB, nullptr, nullptr, 384, 768);

    // gating softmax + top-2 + expert logits / final logits
    gate_kernel<<<BB, 256>>>(bufB, w_r2, b_r2, hs, w_e, b_e, out);

    (void)in_sizes; (void)n_in; (void)out_size;
}

// round 14
// speedup vs baseline: 1.1253x; 1.1253x over previous
#include <cuda_runtime.h>
#include <cuda_bf16.h>
#include <math.h>
#include <stdint.h>

// ---------------- problem constants ----------------
#define BB 256
#define SS 128
#define HH 768
#define NHH 8

// ---------------- scratch (static device globals; no runtime alloc) ----------------
__device__ float g_seqr[BB * HH];
__device__ float g_bufA[BB * 1536];
__device__ float g_bufB[BB * 1536];
__device__ float g_d1o[BB * 384];
__device__ float g_part[4718592];      // split-K partials

// pre-split hi/lo buffers (uint4 for 16B alignment)
__device__ uint4 g_hs_h[3145728],  g_hs_l[3145728];    // 32768*384 w
__device__ uint4 g_wqkv_h[221184], g_wqkv_l[221184];   // 2304*384 w
__device__ uint4 g_wout_h[73728],  g_wout_l[73728];    // 768*384 w
__device__ uint4 g_wf1_h[147456],  g_wf1_l[147456];    // 1536*384 w
__device__ uint4 g_wf2_h[294912],  g_wf2_l[294912];    // 1536*768 w
__device__ uint4 g_wc_h[147456],   g_wc_l[147456];     // 768*768 w
__device__ uint4 g_wr1_h[36864],   g_wr1_l[36864];     // 384*384 w
__device__ uint4 g_wd1_h[36864],   g_wd1_l[36864];     // 384*384 w
__device__ uint4 g_abar_h[24576],  g_abar_l[24576];    // 256*384 w
__device__ uint4 g_seqr_h[24576],  g_seqr_l[24576];    // 256*384 w
__device__ uint4 g_act1_h[49152],  g_act1_l[49152];
__device__ uint4 g_act2_h[49152],  g_act2_l[49152];
__device__ uint4 g_qkvs_h[9437184], g_qkvs_l[9437184]; // 32768*1152 w (split qkv)

// ---------------- bf16x2 split: pair (x0,x1) -> hi word + lo word ----------------
__device__ __forceinline__ void split2(float x0, float x1, uint32_t& h, uint32_t& l) {
    asm("cvt.rn.bf16x2.f32 %0, %1, %2;" : "=r"(h) : "f"(x1), "f"(x0));
    __nv_bfloat162 hb = *reinterpret_cast<__nv_bfloat162*>(&h);
    float h0 = __low2float(hb), h1 = __high2float(hb);
    asm("cvt.rn.bf16x2.f32 %0, %1, %2;" : "=r"(l) : "f"(x1 - h1), "f"(x0 - h0));
}

// ---------------- pre-split kernel ----------------
__global__ void presplit_k(const float* __restrict__ in, int ldaf, int Kf,
                           uint32_t* __restrict__ oh, uint32_t* __restrict__ ol, long total4)
{
    long idx = (long)blockIdx.x * blockDim.x + threadIdx.x;
    if (idx < total4) {
        int K4 = Kf >> 2;
        long row = idx / K4;
        int c4 = (int)(idx - row * K4);
        float4 v = *(const float4*)(in + row * ldaf + c4 * 4);
        uint32_t h0, l0, h1, l1;
        split2(v.x, v.y, h0, l0);
        split2(v.z, v.w, h1, l1);
        long w = row * (Kf >> 1) + c4 * 2;
        oh[w] = h0; oh[w + 1] = h1;
        ol[w] = l0; ol[w + 1] = l1;
    }
}

// ---------------- pipelined bf16x2 GEMM (4-stage, K-tile 16, 1 sync/iter) ----------------
#define SMW 12
#define ARR 1536
#define STG 6144
#define GEMM_SMEM (4 * STG * 4)      // 98304 B

#define CPA(dst, src) \
    asm volatile("cp.async.cg.shared.global [%0], [%1], 16;" :: "r"(dst), "l"(src) : "memory")
#define CP_COMMIT() asm volatile("cp.async.commit_group;" ::: "memory")
#define LDSM4(r0, r1, r2, r3, addr) \
    asm volatile("ldmatrix.sync.aligned.m8n8.x4.shared.b16 {%0,%1,%2,%3}, [%4];" \
                 : "=r"(r0), "=r"(r1), "=r"(r2), "=r"(r3) : "r"(addr))
#define MMA_BF16(acc, a0, a1, a2, a3, b0, b1) \
    asm("mma.sync.aligned.m16n8k16.row.col.f32.bf16.bf16.f32 " \
        "{%0,%1,%2,%3},{%4,%5,%6,%7},{%8,%9},{%0,%1,%2,%3};" \
        : "+f"((acc)[0]), "+f"((acc)[1]), "+f"((acc)[2]), "+f"((acc)[3]) \
        : "r"(a0), "r"(a1), "r"(a2), "r"(a3), "r"(b0), "r"(b1))

// pass-major mma schedule: consecutive mmas target DIFFERENT accumulators
// while per-acc order stays ah*bl -> al*bh -> ah*bh (bit-identical).
#define MMA_TILE_MT(accrow, ah0, ah1, ah2, ah3, al0, al1, al2, al3, bh, bl) do { \
    MMA_BF16((accrow)[0], ah0, ah1, ah2, ah3, (bl)[0][0], (bl)[0][1]); \
    MMA_BF16((accrow)[1], ah0, ah1, ah2, ah3, (bl)[1][0], (bl)[1][1]); \
    MMA_BF16((accrow)[2], ah0, ah1, ah2, ah3, (bl)[2][0], (bl)[2][1]); \
    MMA_BF16((accrow)[3], ah0, ah1, ah2, ah3, (bl)[3][0], (bl)[3][1]); \
    MMA_BF16((accrow)[0], al0, al1, al2, al3, (bh)[0][0], (bh)[0][1]); \
    MMA_BF16((accrow)[1], al0, al1, al2, al3, (bh)[1][0], (bh)[1][1]); \
    MMA_BF16((accrow)[2], al0, al1, al2, al3, (bh)[2][0], (bh)[2][1]); \
    MMA_BF16((accrow)[3], al0, al1, al2, al3, (bh)[3][0], (bh)[3][1]); \
    MMA_BF16((accrow)[0], ah0, ah1, ah2, ah3, (bh)[0][0], (bh)[0][1]); \
    MMA_BF16((accrow)[1], ah0, ah1, ah2, ah3, (bh)[1][0], (bh)[1][1]); \
    MMA_BF16((accrow)[2], ah0, ah1, ah2, ah3, (bh)[2][0], (bh)[2][1]); \
    MMA_BF16((accrow)[3], ah0, ah1, ah2, ah3, (bh)[3][0], (bh)[3][1]); \
} while (0)

// Oh/Ol non-null -> write bf16x2-split output (bias applied); else float C (+bias).
__global__ void __launch_bounds__(256, 2) gemm_sp_k(
    const uint32_t* __restrict__ Ah, const uint32_t* __restrict__ Al, int ldaw,
    const uint32_t* __restrict__ Wh, const uint32_t* __restrict__ Wl, int ldww,
    int kchunkw,
    const float* __restrict__ bias, float* __restrict__ C,
    uint32_t* __restrict__ Oh, uint32_t* __restrict__ Ol,
    int ldc, long sC, int K, int zdiv)
{
    extern __shared__ uint32_t sm[];
    uint32_t smb;
    asm("{ .reg .u64 t; cvta.to.shared.u64 t, %1; cvt.u32.u64 %0, t; }" : "=r"(smb) : "l"(sm));

    int z = blockIdx.z;
    int koffw = (z % zdiv) * kchunkw;

    int tid = threadIdx.x, warp = tid >> 5, lane = tid & 31;
    int wm = warp >> 2, wn = warp & 3, g = lane >> 2, t4 = lane & 3;

    int lr = tid >> 1, hf = tid & 1;
    const uint32_t* pAH = Ah + (long)(blockIdx.y * 128 + lr) * ldaw + koffw + hf * 4;
    const uint32_t* pAL = Al + (long)(blockIdx.y * 128 + lr) * ldaw + koffw + hf * 4;
    const uint32_t* pWH = Wh + (long)(blockIdx.x * 128 + lr) * ldww + koffw + hf * 4;
    const uint32_t* pWL = Wl + (long)(blockIdx.x * 128 + lr) * ldww + koffw + hf * 4;
    uint32_t dstB = smb + (lr * SMW + hf * 4) * 4;

    int laneA = ((lane & 7) + ((lane >> 3) & 1) * 8 + wm * 64) * SMW + ((lane >> 4) & 1) * 4;
    int laneB = ((lane & 7) + ((lane >> 4) & 1) * 8 + wn * 32) * SMW + ((lane >> 3) & 1) * 4;

    float acc[4][4][4];
#pragma unroll
    for (int i = 0; i < 4; i++)
#pragma unroll
        for (int j = 0; j < 4; j++)
#pragma unroll
            for (int e = 0; e < 4; e++) acc[i][j][e] = 0.0f;

    auto prod = [&](int t, int s) {
        uint32_t d = dstB + s * (STG * 4);
        CPA(d,               pAH + t * 8);
        CPA(d + ARR * 4,     pAL + t * 8);
        CPA(d + 2 * ARR * 4, pWH + t * 8);
        CPA(d + 3 * ARR * 4, pWL + t * 8);
    };

    int T = K >> 4;
    prod(0, 0); CP_COMMIT();
    prod(1, 1); CP_COMMIT();
    prod(2, 2); CP_COMMIT();

    for (int t = 0; t < T; t++) {
        asm volatile("cp.async.wait_group 2;" ::: "memory");
        __syncthreads();
        if (t + 3 < T) prod(t + 3, (t + 3) & 3);
        CP_COMMIT();

        uint32_t sb = smb + (t & 3) * (STG * 4);
        uint32_t aH_ = sb + laneA * 4;
        uint32_t aL_ = aH_ + ARR * 4;
        uint32_t bH_ = sb + 2 * ARR * 4 + laneB * 4;
        uint32_t bL_ = bH_ + ARR * 4;

        uint32_t bh[4][2], bl[4][2];
        LDSM4(bh[0][0], bh[0][1], bh[1][0], bh[1][1], bH_);
        LDSM4(bh[2][0], bh[2][1], bh[3][0], bh[3][1], bH_ + 16 * SMW * 4);
        LDSM4(bl[0][0], bl[0][1], bl[1][0], bl[1][1], bL_);
        LDSM4(bl[2][0], bl[2][1], bl[3][0], bl[3][1], bL_ + 16 * SMW * 4);
#pragma unroll
        for (int mt = 0; mt < 4; mt++) {
            uint32_t ah0, ah1, ah2, ah3, al0, al1, al2, al3;
            LDSM4(ah0, ah1, ah2, ah3, aH_ + mt * (16 * SMW * 4));
            LDSM4(al0, al1, al2, al3, aL_ + mt * (16 * SMW * 4));
            MMA_TILE_MT(acc[mt], ah0, ah1, ah2, ah3, al0, al1, al2, al3, bh, bl);
        }
    }

    __syncthreads();
    // epilogue
    if (Oh) {
        int ldcw = ldc >> 1;
#pragma unroll
        for (int mt = 0; mt < 4; mt++) {
            int r0 = wm * 64 + mt * 16 + g;
#pragma unroll
            for (int nt = 0; nt < 4; nt++) {
                int c = wn * 32 + nt * 8 + 2 * t4;
                float b0 = bias ? bias[blockIdx.x * 128 + c] : 0.f;
                float b1 = bias ? bias[blockIdx.x * 128 + c + 1] : 0.f;
                long cw = (long)(blockIdx.x * 128 + c) >> 1;
                uint32_t hw, lw;
                split2(acc[mt][nt][0] + b0, acc[mt][nt][1] + b1, hw, lw);
                long w0 = (long)(blockIdx.y * 128 + r0) * ldcw + cw;
                Oh[w0] = hw; Ol[w0] = lw;
                split2(acc[mt][nt][2] + b0, acc[mt][nt][3] + b1, hw, lw);
                long w1 = (long)(blockIdx.y * 128 + r0 + 8) * ldcw + cw;
                Oh[w1] = hw; Ol[w1] = lw;
            }
        }
    } else {
        float* Cb = C + (long)z * sC + (long)blockIdx.y * 128 * ldc + blockIdx.x * 128;
#pragma unroll
        for (int mt = 0; mt < 4; mt++) {
            int r0 = wm * 64 + mt * 16 + g;
#pragma unroll
            for (int nt = 0; nt < 4; nt++) {
                int c = wn * 32 + nt * 8 + 2 * t4;
                float b0 = 0.f, b1 = 0.f;
                if (bias) { b0 = bias[blockIdx.x * 128 + c]; b1 = bias[blockIdx.x * 128 + c + 1]; }
                float* p0 = Cb + (long)r0 * ldc + c;
                float* p1 = Cb + (long)(r0 + 8) * ldc + c;
                p0[0] = acc[mt][nt][0] + b0; p0[1] = acc[mt][nt][1] + b1;
                p1[0] = acc[mt][nt][2] + b0; p1[1] = acc[mt][nt][3] + b1;
            }
        }
    }
}

// ---------------- fused attention per head, consuming pre-split qkv ----------------
#define ATTN_SMEM GEMM_SMEM
__global__ void __launch_bounds__(256, 2) attn_fused_k(
    const uint32_t* __restrict__ qh, const uint32_t* __restrict__ ql,
    uint32_t* __restrict__ abh, uint32_t* __restrict__ abl)
{
    extern __shared__ uint32_t sm[];
    uint32_t smb;
    asm("{ .reg .u64 t; cvta.to.shared.u64 t, %1; cvt.u32.u64 %0, t; }" : "=r"(smb) : "l"(sm));

    int bhid = blockIdx.x;
    int b = bhid >> 3, h = bhid & 7;

    int tid = threadIdx.x, warp = tid >> 5, lane = tid & 31;
    int wm = warp >> 2, wn = warp & 3, g = lane >> 2, t4 = lane & 3;

    int lr = tid >> 1, hf = tid & 1;
    long rowbase = ((long)b * 128 + lr) * 1152 + h * 48 + hf * 4;
    const uint32_t* pQH = qh + rowbase;
    const uint32_t* pQL = ql + rowbase;
    const uint32_t* pKH = qh + rowbase + 384;
    const uint32_t* pKL = ql + rowbase + 384;
    uint32_t dstB = smb + (lr * SMW + hf * 4) * 4;

    int laneA = ((lane & 7) + ((lane >> 3) & 1) * 8 + wm * 64) * SMW + ((lane >> 4) & 1) * 4;
    int laneB = ((lane & 7) + ((lane >> 4) & 1) * 8 + wn * 32) * SMW + ((lane >> 3) & 1) * 4;

    float acc[4][4][4];
#pragma unroll
    for (int i = 0; i < 4; i++)
#pragma unroll
        for (int j = 0; j < 4; j++)
#pragma unroll
            for (int e = 0; e < 4; e++) acc[i][j][e] = 0.0f;

    auto prod = [&](int t, int s) {
        uint32_t d = dstB + s * (STG * 4);
        CPA(d,               pQH + t * 8);
        CPA(d + ARR * 4,     pQL + t * 8);
        CPA(d + 2 * ARR * 4, pKH + t * 8);
        CPA(d + 3 * ARR * 4, pKL + t * 8);
    };

    const int T = 6;   // K=96 -> 6 k16 tiles
    prod(0, 0); CP_COMMIT();
    prod(1, 1); CP_COMMIT();
    prod(2, 2); CP_COMMIT();

    for (int t = 0; t < T; t++) {
        asm volatile("cp.async.wait_group 2;" ::: "memory");
        __syncthreads();
        if (t + 3 < T) prod(t + 3, (t + 3) & 3);
        CP_COMMIT();

        uint32_t sb = smb + (t & 3) * (STG * 4);
        uint32_t aH_ = sb + laneA * 4;
        uint32_t aL_ = aH_ + ARR * 4;
        uint32_t bH_ = sb + 2 * ARR * 4 + laneB * 4;
        uint32_t bL_ = bH_ + ARR * 4;

        uint32_t bh[4][2], bl[4][2];
        LDSM4(bh[0][0], bh[0][1], bh[1][0], bh[1][1], bH_);
        LDSM4(bh[2][0], bh[2][1], bh[3][0], bh[3][1], bH_ + 16 * SMW * 4);
        LDSM4(bl[0][0], bl[0][1], bl[1][0], bl[1][1], bL_);
        LDSM4(bl[2][0], bl[2][1], bl[3][0], bl[3][1], bL_ + 16 * SMW * 4);
#pragma unroll
        for (int mt = 0; mt < 4; mt++) {
            uint32_t ah0, ah1, ah2, ah3, al0, al1, al2, al3;
            LDSM4(ah0, ah1, ah2, ah3, aH_ + mt * (16 * SMW * 4));
            LDSM4(al0, al1, al2, al3, aL_ + mt * (16 * SMW * 4));
            MMA_TILE_MT(acc[mt], ah0, ah1, ah2, ah3, al0, al1, al2, al3, bh, bl);
        }
    }
    __syncthreads();

    // scaled scores -> smem (stride 132), reusing pipeline smem
    const float scale = 0.10206207261596577f;   // 1/sqrt(96)
    float* sc = (float*)sm;
    float* wa = (float*)(sm + 128 * 132);
    float* wp = wa + 8 * 128;                    // GEMV partials: 4 slices x 96
#pragma unroll
    for (int mt = 0; mt < 4; mt++) {
        int r0 = wm * 64 + mt * 16 + g;
#pragma unroll
        for (int nt = 0; nt < 4; nt++) {
            int c = wn * 32 + nt * 8 + 2 * t4;
            sc[r0 * 132 + c]           = acc[mt][nt][0] * scale;
            sc[r0 * 132 + c + 1]       = acc[mt][nt][1] * scale;
            sc[(r0 + 8) * 132 + c]     = acc[mt][nt][2] * scale;
            sc[(r0 + 8) * 132 + c + 1] = acc[mt][nt][3] * scale;
        }
    }
    __syncthreads();

    // per-row softmax; per-warp column-sum partials (fast exp: MUFU-based)
#pragma unroll
    for (int j = 0; j < 4; j++) wa[warp * 128 + lane + 32 * j] = 0.0f;
    __syncwarp();

    for (int s = warp; s < 128; s += 8) {
        float x0 = sc[s * 132 + lane];
        float x1 = sc[s * 132 + lane + 32];
        float x2 = sc[s * 132 + lane + 64];
        float x3 = sc[s * 132 + lane + 96];
        float m = fmaxf(fmaxf(x0, x1), fmaxf(x2, x3));
#pragma unroll
        for (int o = 16; o; o >>= 1) m = fmaxf(m, __shfl_xor_sync(0xffffffffu, m, o));
        float e0 = __expf(x0 - m), e1 = __expf(x1 - m), e2 = __expf(x2 - m), e3 = __expf(x3 - m);
        float smm = e0 + e1 + e2 + e3;
#pragma unroll
        for (int o = 16; o; o >>= 1) smm += __shfl_xor_sync(0xffffffffu, smm, o);
        float inv = 1.0f / smm;
        wa[warp * 128 + lane]      += e0 * inv;
        wa[warp * 128 + lane + 32] += e1 * inv;
        wa[warp * 128 + lane + 64] += e2 * inv;
        wa[warp * 128 + lane + 96] += e3 * inv;
    }
    __syncthreads();
    if (warp == 0) {
#pragma unroll
        for (int j = 0; j < 4; j++) {
            int c = lane + 32 * j;
            float s = 0.f;
#pragma unroll
            for (int w = 0; w < 8; w++) s += wa[w * 128 + c];
            wa[c] = s;
        }
    }
    __syncthreads();

    // GEMV over v = vh + vl, parallelized: 192 threads = 48 col-pairs x 4 k-slices
    if (tid < 192) {
        int p = tid % 48;
        int ks = tid / 48;
        long vbase = (long)b * 128 * 1152 + 768 + h * 48 + p;
        float a0 = 0.f, a1 = 0.f;
#pragma unroll 4
        for (int k = ks * 32; k < ks * 32 + 32; k++) {
            uint32_t vh = qh[vbase + (long)k * 1152];
            uint32_t vl = ql[vbase + (long)k * 1152];
            __nv_bfloat162 vhb = *reinterpret_cast<__nv_bfloat162*>(&vh);
            __nv_bfloat162 vlb = *reinterpret_cast<__nv_bfloat162*>(&vl);
            float w = wa[k];
            a0 = fmaf(w, __low2float(vhb), a0);
            a0 = fmaf(w, __low2float(vlb), a0);
            a1 = fmaf(w, __high2float(vhb), a1);
            a1 = fmaf(w, __high2float(vlb), a1);
        }
        wp[ks * 96 + 2 * p]     = a0;
        wp[ks * 96 + 2 * p + 1] = a1;
    }
    __syncthreads();
    if (tid < 48) {
        float a0 = ((wp[2 * tid] + wp[96 + 2 * tid]) + wp[192 + 2 * tid]) + wp[288 + 2 * tid];
        float a1 = ((wp[2 * tid + 1] + wp[96 + 2 * tid + 1]) + wp[192 + 2 * tid + 1]) + wp[288 + 2 * tid + 1];
        a0 *= (1.0f / 128.0f);
        a1 *= (1.0f / 128.0f);
        uint32_t hw, lw;
        split2(a0, a1, hw, lw);
        long w = (long)b * 384 + h * 48 + tid;
        abh[w] = hw;
        abl[w] = lw;
    }
}

// ---------------- split-K reduction (pairwise; optional split output) ----------------
__global__ void reduce_k(const float* __restrict__ part, int Z, long stride,
                         const float* __restrict__ bias, int N,
                         float* __restrict__ C, uint32_t* __restrict__ Ch,
                         uint32_t* __restrict__ Cl, int totalPairs)
{
    int p = blockIdx.x * blockDim.x + threadIdx.x;
    if (p < totalPairs) {
        int i0 = 2 * p;
        float s0 = 0.f, s1 = 0.f;
        for (int zz = 0; zz < Z; zz++) {
            s0 += part[(long)zz * stride + i0];
            s1 += part[(long)zz * stride + i0 + 1];
        }
        s0 += bias[i0 % N];
        s1 += bias[(i0 + 1) % N];
        C[i0] = s0; C[i0 + 1] = s1;
        if (Ch) {
            uint32_t hw, lw;
            split2(s0, s1, hw, lw);
            Ch[p] = hw; Cl[p] = lw;
        }
    }
}

// ---------------- fused split-K reduce + LayerNorm + GELU (+ optional split) ----------------
__global__ void redln_k(const float* __restrict__ part, int Z, long stride,
                        const float* __restrict__ bias,
                        const float* __restrict__ gm, const float* __restrict__ be,
                        float* __restrict__ outF,
                        uint32_t* __restrict__ oh, uint32_t* __restrict__ ol, int N)
{
    __shared__ float buf[1536];
    __shared__ float rs[8], rs2[8], sm_mean, sm_rstd;
    int row = blockIdx.x;
    int tid = threadIdx.x, warp = tid >> 5, lane = tid & 31;
    const float* pb = part + (long)row * N;

    float s = 0.f, s2 = 0.f;
    for (int i = tid; i < N; i += blockDim.x) {
        float v = 0.f;
        for (int zz = 0; zz < Z; zz++) v += pb[(long)zz * stride + i];
        v += bias[i];
        buf[i] = v;
        s += v; s2 += v * v;
    }
#pragma unroll
    for (int o = 16; o; o >>= 1) { s += __shfl_xor_sync(0xffffffffu, s, o); s2 += __shfl_xor_sync(0xffffffffu, s2, o); }
    if (lane == 0) { rs[warp] = s; rs2[warp] = s2; }
    __syncthreads();
    if (tid == 0) {
        float S = 0.f, S2 = 0.f;
        for (int w = 0; w < 8; w++) { S += rs[w]; S2 += rs2[w]; }
        float mean = S / N;
        float var = S2 / N - mean * mean;
        sm_mean = mean;
        sm_rstd = rsqrtf(var + 1e-5f);
    }
    __syncthreads();
    float mean = sm_mean, rstd = sm_rstd;
    int half = N >> 1;
    for (int p = tid; p < half; p += blockDim.x) {
        float v0 = (buf[2 * p] - mean) * rstd * gm[2 * p] + be[2 * p];
        float v1 = (buf[2 * p + 1] - mean) * rstd * gm[2 * p + 1] + be[2 * p + 1];
        v0 = 0.5f * v0 * (1.0f + erff(v0 * 0.70710678118654752f));
        v1 = 0.5f * v1 * (1.0f + erff(v1 * 0.70710678118654752f));
        outF[(long)row * N + 2 * p] = v0;
        outF[(long)row * N + 2 * p + 1] = v1;
        if (oh) {
            uint32_t hw, lw;
            split2(v0, v1, hw, lw);
            oh[(long)row * half + p] = hw;
            ol[(long)row * half + p] = lw;
        }
    }
}

// ---------------- warp dot helper ----------------
__device__ __forceinline__ float warp_dot(const float* a, const float* b, int n, int lane)
{
    float s = 0.f;
    for (int i = lane; i < n; i += 32) s = fmaf(a[i], b[i], s);
#pragma unroll
    for (int o = 16; o; o >>= 1) s += __shfl_xor_sync(0xffffffffu, s, o);
    return s;
}

// ---------------- small 5-way head (domain logits) ----------------
__global__ void head5_kernel(const float* __restrict__ in, int Kin,
                             const float* __restrict__ w, const float* __restrict__ bias,
                             float* __restrict__ out)
{
    int b = blockIdx.x, warp = threadIdx.x >> 5, lane = threadIdx.x & 31;
    if (warp < 5) {
        float s = warp_dot(in + (long)b * Kin, w + (long)warp * Kin, Kin, lane);
        if (lane == 0) out[b * 5 + warp] = s + bias[warp];
    }
}

// ---------------- gating softmax + top-2 + expert mix ----------------
__global__ void gate_kernel(const float* __restrict__ r1o,
                            const float* __restrict__ w_r2, const float* __restrict__ b_r2,
                            const float* __restrict__ hs,
                            const float* __restrict__ w_e, const float* __restrict__ b_e,
                            float* __restrict__ out)
{
    __shared__ float gl[5], ae[10];
    int b = blockIdx.x, tid = threadIdx.x, warp = tid >> 5, lane = tid & 31;

    if (warp < 5) {
        float s = warp_dot(r1o + (long)b * 384, w_r2 + (long)warp * 384, 384, lane);
        if (lane == 0) gl[warp] = s + b_r2[warp];
    }
    const float* cls = hs + (long)b * SS * HH;
    for (int idx = warp; idx < 10; idx += 8) {
        float s = warp_dot(cls, w_e + (long)idx * HH, HH, lane);
        if (lane == 0) ae[idx] = s + b_e[idx];
    }
    __syncthreads();

    if (tid == 0) {
        float m = gl[0];
        for (int j = 1; j < 5; j++) m = fmaxf(m, gl[j]);
        float e[5], sum = 0.f;
        for (int j = 0; j < 5; j++) { e[j] = expf(gl[j] - m); sum += e[j]; }
        float p[5];
        for (int j = 0; j < 5; j++) { p[j] = e[j] / sum; out[512 + b * 5 + j] = p[j]; }
        int i1 = 0;
        for (int j = 1; j < 5; j++) if (p[j] > p[i1]) i1 = j;
        int i2 = -1;
        for (int j = 0; j < 5; j++) if (j != i1 && (i2 < 0 || p[j] > p[i2])) i2 = j;
        float ps = p[i1] + p[i2];
        float w1 = p[i1] / ps, w2 = p[i2] / ps;
        for (int ee = 0; ee < 5; ee++) {
            bool sel = (ee == i1) || (ee == i2);
            out[1792 + b * 10 + ee * 2 + 0] = sel ? ae[ee * 2 + 0] : 0.0f;
            out[1792 + b * 10 + ee * 2 + 1] = sel ? ae[ee * 2 + 1] : 0.0f;
        }
        out[b * 2 + 0] = w1 * ae[i1 * 2 + 0] + w2 * ae[i2 * 2 + 0];
        out[b * 2 + 1] = w1 * ae[i1 * 2 + 1] + w2 * ae[i2 * 2 + 1];
    }
}

// ---------------- host launcher ----------------
extern "C" void kernel_launch(void* const* d_in, const int* in_sizes, int n_in,
                              void* d_out, int out_size)
{
    const float* hs    = (const float*)d_in[0];
    const float* w_qkv = (const float*)d_in[1];
    const float* b_qkv = (const float*)d_in[2];
    const float* w_out = (const float*)d_in[3];
    const float* b_out = (const float*)d_in[4];
    const float* w_f1  = (const float*)d_in[5];
    const float* b_f1  = (const float*)d_in[6];
    const float* gf1   = (const float*)d_in[7];
    const float* bef1  = (const float*)d_in[8];
    const float* w_f2  = (const float*)d_in[9];
    const float* b_f2  = (const float*)d_in[10];
    const float* gf2   = (const float*)d_in[11];
    const float* bef2  = (const float*)d_in[12];
    const float* w_c   = (const float*)d_in[13];
    const float* b_c   = (const float*)d_in[14];
    const float* gc    = (const float*)d_in[15];
    const float* bec   = (const float*)d_in[16];
    const float* w_r1  = (const float*)d_in[17];
    const float* b_r1  = (const float*)d_in[18];
    const float* gr1   = (const float*)d_in[19];
    const float* ber1  = (const float*)d_in[20];
    const float* w_r2  = (const float*)d_in[21];
    const float* b_r2  = (const float*)d_in[22];
    const float* w_d1  = (const float*)d_in[23];
    const float* b_d1  = (const float*)d_in[24];
    const float* gd1   = (const float*)d_in[25];
    const float* bed1  = (const float*)d_in[26];
    const float* w_d2  = (const float*)d_in[27];
    const float* b_d2  = (const float*)d_in[28];
    const float* w_e   = (const float*)d_in[29];
    const float* b_e   = (const float*)d_in[30];
    float* out = (float*)d_out;

    float *seqr, *bufA, *bufB, *d1o, *part;
    cudaGetSymbolAddress((void**)&seqr,  g_seqr);
    cudaGetSymbolAddress((void**)&bufA,  g_bufA);
    cudaGetSymbolAddress((void**)&bufB,  g_bufB);
    cudaGetSymbolAddress((void**)&d1o,   g_d1o);
    cudaGetSymbolAddress((void**)&part,  g_part);

    uint32_t *hsh, *hsl, *qkh, *qkl, *outh, *outl, *f1h, *f1l, *f2h, *f2l;
    uint32_t *ch, *cl, *r1h, *r1l, *d1h, *d1l, *abh, *abl, *sqh, *sql;
    uint32_t *a1h, *a1l, *a2h, *a2l, *qvh, *qvl;
    cudaGetSymbolAddress((void**)&hsh, g_hs_h);   cudaGetSymbolAddress((void**)&hsl, g_hs_l);
    cudaGetSymbolAddress((void**)&qkh, g_wqkv_h); cudaGetSymbolAddress((void**)&qkl, g_wqkv_l);
    cudaGetSymbolAddress((void**)&outh, g_wout_h); cudaGetSymbolAddress((void**)&outl, g_wout_l);
    cudaGetSymbolAddress((void**)&f1h, g_wf1_h);  cudaGetSymbolAddress((void**)&f1l, g_wf1_l);
    cudaGetSymbolAddress((void**)&f2h, g_wf2_h);  cudaGetSymbolAddress((void**)&f2l, g_wf2_l);
    cudaGetSymbolAddress((void**)&ch,  g_wc_h);   cudaGetSymbolAddress((void**)&cl,  g_wc_l);
    cudaGetSymbolAddress((void**)&r1h, g_wr1_h);  cudaGetSymbolAddress((void**)&r1l, g_wr1_l);
    cudaGetSymbolAddress((void**)&d1h, g_wd1_h);  cudaGetSymbolAddress((void**)&d1l, g_wd1_l);
    cudaGetSymbolAddress((void**)&abh, g_abar_h); cudaGetSymbolAddress((void**)&abl, g_abar_l);
    cudaGetSymbolAddress((void**)&sqh, g_seqr_h); cudaGetSymbolAddress((void**)&sql, g_seqr_l);
    cudaGetSymbolAddress((void**)&a1h, g_act1_h); cudaGetSymbolAddress((void**)&a1l, g_act1_l);
    cudaGetSymbolAddress((void**)&a2h, g_act2_h); cudaGetSymbolAddress((void**)&a2l, g_act2_l);
    cudaGetSymbolAddress((void**)&qvh, g_qkvs_h); cudaGetSymbolAddress((void**)&qvl, g_qkvs_l);

    cudaFuncSetAttribute(gemm_sp_k,    cudaFuncAttributeMaxDynamicSharedMemorySize, GEMM_SMEM);
    cudaFuncSetAttribute(attn_fused_k, cudaFuncAttributeMaxDynamicSharedMemorySize, ATTN_SMEM);

    auto split = [&](const float* in, int lda, int M, int K, uint32_t* oh, uint32_t* ol) {
        long t4 = (long)M * K / 4;
        presplit_k<<<(unsigned)((t4 + 255) / 256), 256>>>(in, lda, K, oh, ol, t4);
    };

    // 0-2: pre-split hs / w_qkv / w_d1  (qkv at launch idx 3 for ncu capture)
    split(hs,    768, 32768, 768, hsh, hsl);
    split(w_qkv, 768, 2304,  768, qkh, qkl);
    split(w_d1,  768, 384,   768, d1h, d1l);

    // 3: qkv = hs @ w_qkv.T + b_qkv  -> split output directly
    gemm_sp_k<<<dim3(18, 256, 1), 256, GEMM_SMEM>>>(
        hsh, hsl, 384, qkh, qkl, 384, 0, b_qkv, nullptr, qvh, qvl, 2304, 0, 768, 1);

    // remaining weight pre-splits
    split(w_out, 768,  768,  768,  outh, outl);
    split(w_f1,  768,  1536, 768,  f1h,  f1l);
    split(w_f2,  1536, 1536, 1536, f2h,  f2l);
    split(w_c,   1536, 768,  1536, ch,   cl);
    split(w_r1,  768,  384,  768,  r1h,  r1l);

    // split-K GEMM (Kc = 128 -> kchunkw = 64) -> float partials
    auto gemm_part = [&](const uint32_t* Ah, const uint32_t* Al, int ldaw,
                         const uint32_t* Wh, const uint32_t* Wl, int ldww,
                         int N, int K) {
        int Z = K / 128;
        dim3 grid(N / 128, BB / 128, Z);
        gemm_sp_k<<<grid, 256, GEMM_SMEM>>>(
            Ah, Al, ldaw, Wh, Wl, ldww, 64, nullptr, part, nullptr, nullptr,
            N, (long)BB * N, 128, Z);
        return Z;
    };

    auto gemm_ln = [&](const uint32_t* Ah, const uint32_t* Al, int ldaw,
                       const uint32_t* Wh, const uint32_t* Wl, int ldww,
                       const float* bias, const float* gm, const float* be,
                       float* outF, uint32_t* oh, uint32_t* ol, int N, int K) {
        int Z = gemm_part(Ah, Al, ldaw, Wh, Wl, ldww, N, K);
        redln_k<<<BB, 256>>>(part, Z, (long)BB * N, bias, gm, be, outF, oh, ol, N);
    };

    // domain path
    gemm_ln(hsh, hsl, SS * 384, d1h, d1l, 384, b_d1, gd1, bed1, d1o, nullptr, nullptr, 384, 768);
    head5_kernel<<<BB, 160>>>(d1o, 384, w_d2, b_d2, out + 4352);

    // fused attention (pre-split qkv) -> abar (split)
    attn_fused_k<<<BB * NHH, 256, ATTN_SMEM>>>(qvh, qvl, abh, abl);

    // seq_repr = abar @ w_out.T + b_out
    {
        int Z = gemm_part(abh, abl, 384, outh, outl, 384, 768, 768);
        int pairs = BB * 768 / 2;
        reduce_k<<<(pairs + 255) / 256, 256>>>(part, Z, (long)BB * 768, b_out, 768,
                                               seqr, sqh, sql, pairs);
    }

    // f1 -> f2 -> ctx -> r1 chain
    gemm_ln(sqh, sql, 384, f1h, f1l, 384, b_f1, gf1, bef1, bufA, a1h, a1l, 1536, 768);
    gemm_ln(a1h, a1l, 768, f2h, f2l, 768, b_f2, gf2, bef2, bufA, a2h, a2l, 1536, 1536);
    gemm_ln(a2h, a2l, 768, ch, cl, 768, b_c, gc, bec, bufA, a1h, a1l, 768, 1536);
    gemm_ln(a1h, a1l, 384, r1h, r1l, 384, b_r1, gr1, ber1, bufB, nullptr, nullptr, 384, 768);

    // gating softmax + top-2 + expert logits / final logits
    gate_kernel<<<BB, 256>>>(bufB, w_r2, b_r2, hs, w_e, b_e, out);

    (void)in_sizes; (void)n_in; (void)out_size;
}